// round 1
// baseline (speedup 1.0000x reference)
#include <cuda_runtime.h>
#include <math.h>

#define N_ROWS      4096
#define NUM_CLASSES 751
#define D_FEAT      2048
#define MARGIN1     0.5f
#define NTILE       32          // 4096 / 128
#define NBLOCKS_TRI (NTILE * (NTILE + 1) / 2)   // 528

// ---------------- scratch (device globals; no allocations allowed) ----------
__device__ float    g_sq[N_ROWS];
__device__ float    g_xrow[N_ROWS];
__device__ unsigned g_min_an[N_ROWS];   // bits of min cross-class d^2 (positive floats)
__device__ unsigned g_max_ap[N_ROWS];   // bits of max same-class  d^2

// ---------------- packed f32x2 helpers (FFMA2 path) -------------------------
__device__ __forceinline__ void ffma2(unsigned long long& d,
                                      unsigned long long a,
                                      unsigned long long b) {
    asm("fma.rn.f32x2 %0, %1, %2, %0;" : "+l"(d) : "l"(a), "l"(b));
}
__device__ __forceinline__ unsigned long long pack2(float x) {
    unsigned long long r;
    asm("mov.b64 %0, {%1, %1};" : "=l"(r) : "f"(x));
    return r;
}
__device__ __forceinline__ float2 unpack2(unsigned long long v) {
    float2 f;
    asm("mov.b64 {%0, %1}, %2;" : "=f"(f.x), "=f"(f.y) : "l"(v));
    return f;
}

// ---------------- block reductions (blockDim.x == 256) ----------------------
__device__ __forceinline__ float blockReduceSum(float v) {
    __shared__ float red[8];
    __shared__ float bc;
    int lane = threadIdx.x & 31, wid = threadIdx.x >> 5;
    #pragma unroll
    for (int s = 16; s; s >>= 1) v += __shfl_xor_sync(0xffffffffu, v, s);
    if (lane == 0) red[wid] = v;
    __syncthreads();
    if (threadIdx.x == 0) {
        float r = 0.f;
        #pragma unroll
        for (int w = 0; w < 8; ++w) r += red[w];
        bc = r;
    }
    __syncthreads();
    return bc;
}
__device__ __forceinline__ float blockReduceMax(float v) {
    __shared__ float red[8];
    __shared__ float bc;
    int lane = threadIdx.x & 31, wid = threadIdx.x >> 5;
    #pragma unroll
    for (int s = 16; s; s >>= 1) v = fmaxf(v, __shfl_xor_sync(0xffffffffu, v, s));
    if (lane == 0) red[wid] = v;
    __syncthreads();
    if (threadIdx.x == 0) {
        float r = -1e30f;
        #pragma unroll
        for (int w = 0; w < 8; ++w) r = fmaxf(r, red[w]);
        bc = r;
    }
    __syncthreads();
    return bc;
}

// ---------------- init ------------------------------------------------------
__global__ void init_kernel() {
    int i = blockIdx.x * blockDim.x + threadIdx.x;
    if (i < N_ROWS) {
        g_min_an[i] = 0x7F800000u;  // +inf
        g_max_ap[i] = 0u;           // 0.0f
    }
}

// ---------------- per-row squared norms --------------------------------------
__global__ void sq_kernel(const float* __restrict__ feat) {
    int row = blockIdx.x;
    const float4* f = reinterpret_cast<const float4*>(feat + (size_t)row * D_FEAT);
    int t = threadIdx.x;
    float s = 0.f;
    #pragma unroll
    for (int q = 0; q < 2; ++q) {
        float4 v = f[t + q * 256];
        s += v.x * v.x + v.y * v.y + v.z * v.z + v.w * v.w;
    }
    s = blockReduceSum(s);
    if (t == 0) g_sq[row] = s;
}

// ---------------- per-row cross-entropy term ---------------------------------
__global__ void xent_kernel(const float* __restrict__ logits,
                            const int*   __restrict__ targets) {
    int row = blockIdx.x;
    const float* lr = logits + (size_t)row * NUM_CLASSES;
    float m = -1e30f;
    for (int c = threadIdx.x; c < NUM_CLASSES; c += 256) m = fmaxf(m, lr[c]);
    m = blockReduceMax(m);
    float s = 0.f;
    for (int c = threadIdx.x; c < NUM_CLASSES; c += 256) s += expf(lr[c] - m);
    s = blockReduceSum(s);
    if (threadIdx.x == 0)
        g_xrow[row] = m + logf(s) - lr[targets[row]];
}

// ---------------- fused Gram GEMM + batch-hard mining ------------------------
// Upper-triangular 128x128 tiles: block t -> (a,b), a<=b.
// acc = F[i,:] . F[j,:] via packed f32x2 FMAs (8x8 per thread, BK=16).
__global__ __launch_bounds__(256) void gemm_mine_kernel(const float* __restrict__ feat) {
    __shared__ float As[16][128];
    __shared__ float Bs[16][128];

    // triangular decode
    int t = blockIdx.x;
    int a = 0;
    while (t >= (NTILE - a)) { t -= (NTILE - a); ++a; }
    int b = a + t;
    const bool diag = (a == b);

    const int i0 = a * 128, j0 = b * 128;
    const int tid = threadIdx.x;
    const int lr  = tid >> 2;        // 0..63 (load row)
    const int lc  = (tid & 3) * 4;   // 0,4,8,12 (load col within BK)
    const int ty  = tid >> 4;        // 0..15
    const int tx  = tid & 15;        // 0..15

    const float* gA = feat + (size_t)(i0 + lr) * D_FEAT + lc;
    const float* gB = feat + (size_t)(j0 + lr) * D_FEAT + lc;

    unsigned long long accp[8][4];
    #pragma unroll
    for (int r = 0; r < 8; ++r)
        #pragma unroll
        for (int c = 0; c < 4; ++c) accp[r][c] = 0ull;

    // first tile prefetch
    float4 pa0 = *reinterpret_cast<const float4*>(gA);
    float4 pa1 = *reinterpret_cast<const float4*>(gA + 64 * D_FEAT);
    float4 pb0 = *reinterpret_cast<const float4*>(gB);
    float4 pb1 = *reinterpret_cast<const float4*>(gB + 64 * D_FEAT);

    for (int kk = 0; kk < D_FEAT; kk += 16) {
        // commit prefetched tile to smem (K-major transposed)
        As[lc + 0][lr]      = pa0.x; As[lc + 1][lr]      = pa0.y;
        As[lc + 2][lr]      = pa0.z; As[lc + 3][lr]      = pa0.w;
        As[lc + 0][lr + 64] = pa1.x; As[lc + 1][lr + 64] = pa1.y;
        As[lc + 2][lr + 64] = pa1.z; As[lc + 3][lr + 64] = pa1.w;
        Bs[lc + 0][lr]      = pb0.x; Bs[lc + 1][lr]      = pb0.y;
        Bs[lc + 2][lr]      = pb0.z; Bs[lc + 3][lr]      = pb0.w;
        Bs[lc + 0][lr + 64] = pb1.x; Bs[lc + 1][lr + 64] = pb1.y;
        Bs[lc + 2][lr + 64] = pb1.z; Bs[lc + 3][lr + 64] = pb1.w;
        __syncthreads();

        if (kk + 16 < D_FEAT) {
            pa0 = *reinterpret_cast<const float4*>(gA + kk + 16);
            pa1 = *reinterpret_cast<const float4*>(gA + 64 * D_FEAT + kk + 16);
            pb0 = *reinterpret_cast<const float4*>(gB + kk + 16);
            pb1 = *reinterpret_cast<const float4*>(gB + 64 * D_FEAT + kk + 16);
        }

        #pragma unroll
        for (int k = 0; k < 16; ++k) {
            float4 a0 = *reinterpret_cast<const float4*>(&As[k][ty * 8]);
            float4 a1 = *reinterpret_cast<const float4*>(&As[k][ty * 8 + 4]);
            ulonglong2 b0 = *reinterpret_cast<const ulonglong2*>(&Bs[k][tx * 8]);
            ulonglong2 b1 = *reinterpret_cast<const ulonglong2*>(&Bs[k][tx * 8 + 4]);
            unsigned long long bp0 = b0.x, bp1 = b0.y, bp2 = b1.x, bp3 = b1.y;
            float av[8] = {a0.x, a0.y, a0.z, a0.w, a1.x, a1.y, a1.z, a1.w};
            #pragma unroll
            for (int r = 0; r < 8; ++r) {
                unsigned long long aa = pack2(av[r]);
                ffma2(accp[r][0], aa, bp0);
                ffma2(accp[r][1], aa, bp1);
                ffma2(accp[r][2], aa, bp2);
                ffma2(accp[r][3], aa, bp3);
            }
        }
        __syncthreads();
    }

    // ---------------- epilogue: d^2 + hard mining ---------------------------
    float sqj[8];
    #pragma unroll
    for (int c = 0; c < 8; ++c) sqj[c] = g_sq[j0 + tx * 8 + c];

    float colmin[8];
    #pragma unroll
    for (int c = 0; c < 8; ++c) colmin[c] = 1e30f;

    #pragma unroll
    for (int r = 0; r < 8; ++r) {
        const int li = ty * 8 + r;
        const int i  = i0 + li;
        const float sqi = g_sq[i];
        float rmin = 1e30f, rmax = 0.f;
        #pragma unroll
        for (int cc = 0; cc < 4; ++cc) {
            float2 d = unpack2(accp[r][cc]);
            const int c0 = 2 * cc, c1 = 2 * cc + 1;
            float d2a = fmaxf(sqi + sqj[c0] - 2.f * d.x, 0.f);
            float d2b = fmaxf(sqi + sqj[c1] - 2.f * d.y, 0.f);
            if (diag) {
                const int lj0 = tx * 8 + c0;
                const bool s0 = (li >> 2) == (lj0 >> 2);
                const bool s1 = (li >> 2) == ((lj0 + 1) >> 2);
                if (s0) rmax = fmaxf(rmax, d2a); else rmin = fminf(rmin, d2a);
                if (s1) rmax = fmaxf(rmax, d2b); else rmin = fminf(rmin, d2b);
            } else {
                rmin = fminf(rmin, d2a);
                rmin = fminf(rmin, d2b);
                colmin[c0] = fminf(colmin[c0], d2a);
                colmin[c1] = fminf(colmin[c1], d2b);
            }
        }
        // reduce across the 16 lanes sharing these rows (xor<=8 stays in half-warp)
        #pragma unroll
        for (int s = 8; s; s >>= 1) {
            rmin = fminf(rmin, __shfl_xor_sync(0xffffffffu, rmin, s));
            rmax = fmaxf(rmax, __shfl_xor_sync(0xffffffffu, rmax, s));
        }
        if (tx == 0) {
            atomicMin(&g_min_an[i], __float_as_uint(rmin));
            if (diag) atomicMax(&g_max_ap[i], __float_as_uint(rmax));
        }
    }

    // column-side (symmetric) stats for off-diagonal tiles
    if (!diag) {
        __syncthreads();
        float* Cs = &As[0][0];   // reuse 16x128 smem
        #pragma unroll
        for (int c = 0; c < 8; ++c) Cs[ty * 128 + tx * 8 + c] = colmin[c];
        __syncthreads();
        if (tid < 128) {
            float m = 1e30f;
            #pragma unroll
            for (int u = 0; u < 16; ++u) m = fminf(m, Cs[u * 128 + tid]);
            atomicMin(&g_min_an[j0 + tid], __float_as_uint(m));
        }
    }
}

// ---------------- final scalar -----------------------------------------------
__global__ void finalize_kernel(float* __restrict__ out) {
    float xs = 0.f, ts = 0.f;
    for (int i = threadIdx.x; i < N_ROWS; i += 256) {
        xs += g_xrow[i];
        float ap = sqrtf(fmaxf(__uint_as_float(g_max_ap[i]), 1e-12f));
        float an = sqrtf(fmaxf(__uint_as_float(g_min_an[i]), 1e-12f));
        ts += fmaxf(ap - an + MARGIN1, 0.f);
    }
    xs = blockReduceSum(xs);
    ts = blockReduceSum(ts);
    if (threadIdx.x == 0) out[0] = xs / (float)N_ROWS + ts / (float)N_ROWS;
}

// ---------------- launch ------------------------------------------------------
extern "C" void kernel_launch(void* const* d_in, const int* in_sizes, int n_in,
                              void* d_out, int out_size) {
    const float* logits  = (const float*)d_in[0];
    const float* feat    = (const float*)d_in[1];
    const int*   targets = (const int*)d_in[2];
    float* out = (float*)d_out;

    init_kernel<<<(N_ROWS + 255) / 256, 256>>>();
    sq_kernel<<<N_ROWS, 256>>>(feat);
    xent_kernel<<<N_ROWS, 256>>>(logits, targets);
    gemm_mine_kernel<<<NBLOCKS_TRI, 256>>>(feat);
    finalize_kernel<<<1, 256>>>(out);
}

// round 3
// speedup vs baseline: 3.2691x; 3.2691x over previous
#include <cuda_runtime.h>
#include <math.h>
#include <stdint.h>

#define N_ROWS      4096
#define NUM_CLASSES 751
#define D_FEAT      2048
#define MARGIN1     0.5f
#define NTILE       32
#define NBLOCKS_TRI 528
#define KC          32
#define CHUNKS      (D_FEAT / KC)     // 64
#define STAGES      3
#define LDA         36                // padded row stride (floats)
#define STAGE_FLOATS (128 * LDA)      // 4608
#define STAGE_BYTES  (STAGE_FLOATS * 4)   // 18432
#define SMEM_BYTES   (2 * STAGES * STAGE_BYTES)  // 110592

// ---------------- device scratch ---------------------------------------------
__device__ float    g_feat_t[(size_t)N_ROWS * D_FEAT];   // tf32-rounded features
__device__ float    g_sq[N_ROWS];
__device__ float    g_xrow[N_ROWS];
__device__ unsigned g_min_an[N_ROWS];
__device__ unsigned g_max_ap[N_ROWS];

// ---------------- PTX helpers -------------------------------------------------
__device__ __forceinline__ uint32_t smem_u32(const void* p) {
    uint32_t a;
    asm("{ .reg .u64 t; cvta.to.shared.u64 t, %1; cvt.u32.u64 %0, t; }"
        : "=r"(a) : "l"(p));
    return a;
}
__device__ __forceinline__ void cpasync16(uint32_t dst, const void* src) {
    asm volatile("cp.async.cg.shared.global [%0], [%1], 16;" :: "r"(dst), "l"(src));
}
__device__ __forceinline__ void mma_tf32_16x8x8(float* c, const uint32_t* a,
                                                const uint32_t* b) {
    asm volatile(
        "mma.sync.aligned.m16n8k8.row.col.f32.tf32.tf32.f32 "
        "{%0,%1,%2,%3}, {%4,%5,%6,%7}, {%8,%9}, {%0,%1,%2,%3};"
        : "+f"(c[0]), "+f"(c[1]), "+f"(c[2]), "+f"(c[3])
        : "r"(a[0]), "r"(a[1]), "r"(a[2]), "r"(a[3]), "r"(b[0]), "r"(b[1]));
}

// ---------------- block reductions (blockDim.x == 256) ------------------------
__device__ __forceinline__ float blockReduceSum(float v) {
    __shared__ float red[8];
    __shared__ float bc;
    int lane = threadIdx.x & 31, wid = threadIdx.x >> 5;
    #pragma unroll
    for (int s = 16; s; s >>= 1) v += __shfl_xor_sync(0xffffffffu, v, s);
    if (lane == 0) red[wid] = v;
    __syncthreads();
    if (threadIdx.x == 0) {
        float r = 0.f;
        #pragma unroll
        for (int w = 0; w < 8; ++w) r += red[w];
        bc = r;
    }
    __syncthreads();
    return bc;
}
__device__ __forceinline__ float blockReduceMax(float v) {
    __shared__ float red[8];
    __shared__ float bc;
    int lane = threadIdx.x & 31, wid = threadIdx.x >> 5;
    #pragma unroll
    for (int s = 16; s; s >>= 1) v = fmaxf(v, __shfl_xor_sync(0xffffffffu, v, s));
    if (lane == 0) red[wid] = v;
    __syncthreads();
    if (threadIdx.x == 0) {
        float r = -1e30f;
        #pragma unroll
        for (int w = 0; w < 8; ++w) r = fmaxf(r, red[w]);
        bc = r;
    }
    __syncthreads();
    return bc;
}

// ---------------- sq + tf32 convert + init ------------------------------------
__device__ __forceinline__ float tf32_rn(float x) {
    uint32_t b;
    asm("cvt.rna.tf32.f32 %0, %1;" : "=r"(b) : "f"(x));
    return __uint_as_float(b);
}
__global__ void sq_cvt_kernel(const float* __restrict__ feat) {
    int row = blockIdx.x;
    const float4* f = reinterpret_cast<const float4*>(feat + (size_t)row * D_FEAT);
    float4* o = reinterpret_cast<float4*>(g_feat_t + (size_t)row * D_FEAT);
    int t = threadIdx.x;
    float s = 0.f;
    #pragma unroll
    for (int q = 0; q < 2; ++q) {
        float4 v = f[t + q * 256];
        s += v.x * v.x + v.y * v.y + v.z * v.z + v.w * v.w;
        float4 w;
        w.x = tf32_rn(v.x); w.y = tf32_rn(v.y);
        w.z = tf32_rn(v.z); w.w = tf32_rn(v.w);
        o[t + q * 256] = w;
    }
    s = blockReduceSum(s);
    if (t == 0) {
        g_sq[row] = s;
        g_min_an[row] = 0x7F800000u;   // +inf
        g_max_ap[row] = 0u;
    }
}

// ---------------- per-row cross-entropy ---------------------------------------
__global__ void xent_kernel(const float* __restrict__ logits,
                            const int*   __restrict__ targets) {
    int row = blockIdx.x;
    const float* lr = logits + (size_t)row * NUM_CLASSES;
    float m = -1e30f;
    for (int c = threadIdx.x; c < NUM_CLASSES; c += 256) m = fmaxf(m, lr[c]);
    m = blockReduceMax(m);
    float s = 0.f;
    for (int c = threadIdx.x; c < NUM_CLASSES; c += 256) s += expf(lr[c] - m);
    s = blockReduceSum(s);
    if (threadIdx.x == 0)
        g_xrow[row] = m + logf(s) - lr[targets[row]];
}

// ---------------- HMMA tf32 Gram GEMM + batch-hard mining ---------------------
__global__ __launch_bounds__(256, 2) void gemm_mine_hmma() {
    extern __shared__ float sm[];
    const int tid  = threadIdx.x;
    const int lane = tid & 31;
    const int wid  = tid >> 5;
    const int wm   = wid >> 1;       // 0..3  (M warps)
    const int wn   = wid & 1;        // 0..1  (N warps)
    const int grp  = lane >> 2;      // 0..7
    const int tig  = lane & 3;       // 0..3

    // triangular tile decode
    int t = blockIdx.x, a = 0;
    while (t >= NTILE - a) { t -= NTILE - a; ++a; }
    const int b = a + t;
    const bool diag = (a == b);
    const int i0 = a * 128, j0 = b * 128;

    // ----- load indexing: each thread loads 4x16B per matrix per chunk -------
    const int rb = tid >> 3;          // 0..31
    const int q  = tid & 7;           // 0..7
    const float* pA = g_feat_t + (size_t)(i0 + rb) * D_FEAT + q * 4;
    const float* pB = g_feat_t + (size_t)(j0 + rb) * D_FEAT + q * 4;
    const uint32_t base = smem_u32(sm);
    const uint32_t ldst = (uint32_t)(rb * LDA + q * 4) * 4;
    const uint32_t smA = base, smB = base + STAGES * STAGE_BYTES;

    auto load_chunk = [&](int s, int c) {
        const float* aa = pA + c * KC;
        const float* bb = pB + c * KC;
        const uint32_t da = smA + s * STAGE_BYTES + ldst;
        const uint32_t db = smB + s * STAGE_BYTES + ldst;
        #pragma unroll
        for (int u = 0; u < 4; ++u) {
            cpasync16(da + u * 32 * LDA * 4, aa + (size_t)u * 32 * D_FEAT);
            cpasync16(db + u * 32 * LDA * 4, bb + (size_t)u * 32 * D_FEAT);
        }
        asm volatile("cp.async.commit_group;" ::: "memory");
    };

    float acc[2][8][4];
    #pragma unroll
    for (int mf = 0; mf < 2; ++mf)
        #pragma unroll
        for (int nf = 0; nf < 8; ++nf)
            #pragma unroll
            for (int r = 0; r < 4; ++r) acc[mf][nf][r] = 0.f;

    load_chunk(0, 0);
    load_chunk(1, 1);

    for (int c = 0; c < CHUNKS; ++c) {
        const int s = c % STAGES;
        asm volatile("cp.async.wait_group 1;" ::: "memory");
        __syncthreads();
        if (c + STAGES - 1 < CHUNKS)
            load_chunk((c + STAGES - 1) % STAGES, c + STAGES - 1);

        const float* As = sm + s * STAGE_FLOATS;
        const float* Bs = sm + STAGES * STAGE_FLOATS + s * STAGE_FLOATS;

        #pragma unroll
        for (int k8 = 0; k8 < 4; ++k8) {
            const int kb = k8 * 8;
            uint32_t av[2][4], bv[8][2];
            #pragma unroll
            for (int mf = 0; mf < 2; ++mf) {
                const float* ap = As + (wm * 32 + mf * 16 + grp) * LDA + kb + tig;
                av[mf][0] = __float_as_uint(ap[0]);
                av[mf][1] = __float_as_uint(ap[8 * LDA]);
                av[mf][2] = __float_as_uint(ap[4]);
                av[mf][3] = __float_as_uint(ap[8 * LDA + 4]);
            }
            #pragma unroll
            for (int nf = 0; nf < 8; ++nf) {
                const float* bp = Bs + (wn * 64 + nf * 8 + grp) * LDA + kb + tig;
                bv[nf][0] = __float_as_uint(bp[0]);
                bv[nf][1] = __float_as_uint(bp[4]);
            }
            #pragma unroll
            for (int mf = 0; mf < 2; ++mf)
                #pragma unroll
                for (int nf = 0; nf < 8; ++nf)
                    mma_tf32_16x8x8(acc[mf][nf], av[mf], bv[nf]);
        }
    }

    // ---------------- epilogue: d^2 + batch-hard mining ----------------------
    __syncthreads();
    unsigned* rminS = (unsigned*)sm;
    unsigned* rmaxS = rminS + 128;
    unsigned* cminS = rminS + 256;
    if (tid < 128) {
        rminS[tid] = 0x7F800000u;
        rmaxS[tid] = 0u;
        cminS[tid] = 0x7F800000u;
    }
    __syncthreads();

    const int ib = i0 + wm * 32 + grp;       // + mf*16 (+8)
    const int jb = j0 + wn * 64 + 2 * tig;   // + nf*8 (+p)

    float sqj[8][2];
    #pragma unroll
    for (int nf = 0; nf < 8; ++nf) {
        sqj[nf][0] = __ldg(&g_sq[jb + nf * 8]);
        sqj[nf][1] = __ldg(&g_sq[jb + nf * 8 + 1]);
    }

    float cl[8][2];
    #pragma unroll
    for (int nf = 0; nf < 8; ++nf) { cl[nf][0] = 1e30f; cl[nf][1] = 1e30f; }

    #pragma unroll
    for (int mf = 0; mf < 2; ++mf) {
        const int iA = ib + mf * 16, iB = iA + 8;
        const float sq0 = __ldg(&g_sq[iA]);
        const float sq1 = __ldg(&g_sq[iB]);
        float rm0 = 1e30f, rm1 = 1e30f, rx0 = 0.f, rx1 = 0.f;
        #pragma unroll
        for (int nf = 0; nf < 8; ++nf) {
            #pragma unroll
            for (int p = 0; p < 2; ++p) {
                const int j = jb + nf * 8 + p;
                float d0 = fmaxf(sq0 + sqj[nf][p] - 2.f * acc[mf][nf][p],     0.f);
                float d1 = fmaxf(sq1 + sqj[nf][p] - 2.f * acc[mf][nf][2 + p], 0.f);
                if (diag) {
                    bool s0 = (iA >> 2) == (j >> 2);
                    bool s1 = (iB >> 2) == (j >> 2);
                    if (s0) rx0 = fmaxf(rx0, d0); else rm0 = fminf(rm0, d0);
                    if (s1) rx1 = fmaxf(rx1, d1); else rm1 = fminf(rm1, d1);
                } else {
                    rm0 = fminf(rm0, d0);
                    rm1 = fminf(rm1, d1);
                    cl[nf][p] = fminf(cl[nf][p], fminf(d0, d1));
                }
            }
        }
        #pragma unroll
        for (int sft = 1; sft <= 2; sft <<= 1) {
            rm0 = fminf(rm0, __shfl_xor_sync(0xffffffffu, rm0, sft));
            rm1 = fminf(rm1, __shfl_xor_sync(0xffffffffu, rm1, sft));
            rx0 = fmaxf(rx0, __shfl_xor_sync(0xffffffffu, rx0, sft));
            rx1 = fmaxf(rx1, __shfl_xor_sync(0xffffffffu, rx1, sft));
        }
        if (tig == 0) {
            atomicMin(&rminS[iA - i0], __float_as_uint(rm0));
            atomicMin(&rminS[iB - i0], __float_as_uint(rm1));
            if (diag) {
                atomicMax(&rmaxS[iA - i0], __float_as_uint(rx0));
                atomicMax(&rmaxS[iB - i0], __float_as_uint(rx1));
            }
        }
    }

    if (!diag) {
        #pragma unroll
        for (int nf = 0; nf < 8; ++nf)
            #pragma unroll
            for (int p = 0; p < 2; ++p) {
                float v = cl[nf][p];
                #pragma unroll
                for (int sft = 4; sft <= 16; sft <<= 1)
                    v = fminf(v, __shfl_xor_sync(0xffffffffu, v, sft));
                if (grp == 0)
                    atomicMin(&cminS[wn * 64 + nf * 8 + 2 * tig + p],
                              __float_as_uint(v));
            }
    }

    __syncthreads();
    if (tid < 128) {
        atomicMin(&g_min_an[i0 + tid], rminS[tid]);
        if (diag) atomicMax(&g_max_ap[i0 + tid], rmaxS[tid]);
        else      atomicMin(&g_min_an[j0 + tid], cminS[tid]);
    }
}

// ---------------- final scalar -------------------------------------------------
__global__ void finalize_kernel(float* __restrict__ out) {
    float xs = 0.f, ts = 0.f;
    for (int i = threadIdx.x; i < N_ROWS; i += 256) {
        xs += g_xrow[i];
        float ap = sqrtf(fmaxf(__uint_as_float(g_max_ap[i]), 1e-12f));
        float an = sqrtf(fmaxf(__uint_as_float(g_min_an[i]), 1e-12f));
        ts += fmaxf(ap - an + MARGIN1, 0.f);
    }
    xs = blockReduceSum(xs);
    ts = blockReduceSum(ts);
    if (threadIdx.x == 0) out[0] = xs / (float)N_ROWS + ts / (float)N_ROWS;
}

// ---------------- launch --------------------------------------------------------
extern "C" void kernel_launch(void* const* d_in, const int* in_sizes, int n_in,
                              void* d_out, int out_size) {
    const float* logits  = (const float*)d_in[0];
    const float* feat    = (const float*)d_in[1];
    const int*   targets = (const int*)d_in[2];
    float* out = (float*)d_out;

    cudaFuncSetAttribute(gemm_mine_hmma,
                         cudaFuncAttributeMaxDynamicSharedMemorySize, SMEM_BYTES);

    sq_cvt_kernel<<<N_ROWS, 256>>>(feat);
    xent_kernel<<<N_ROWS, 256>>>(logits, targets);
    gemm_mine_hmma<<<NBLOCKS_TRI, 256, SMEM_BYTES>>>();
    finalize_kernel<<<1, 256>>>(out);
}

// round 4
// speedup vs baseline: 5.3333x; 1.6314x over previous
#include <cuda_runtime.h>
#include <cuda_fp16.h>
#include <math.h>
#include <stdint.h>

#define N_ROWS      4096
#define NUM_CLASSES 751
#define D_FEAT      2048
#define MARGIN1     0.5f
#define NTILE       32
#define NBLOCKS_TRI 528
#define KC          32                    // halfs per k-chunk (64 B/row)
#define CHUNKS      (D_FEAT / KC)         // 64
#define STAGES      3
#define LDH         40                    // padded smem row stride (halfs)
#define STAGE_HALFS (128 * LDH)           // 5120
#define STAGE_BYTES (STAGE_HALFS * 2)     // 10240
#define SMEM_BYTES  (2 * STAGES * STAGE_BYTES)  // 61440
#define FIN_BLOCKS  16

// ---------------- device scratch ---------------------------------------------
__device__ __half   g_feat_h[(size_t)N_ROWS * D_FEAT];
__device__ float    g_sq[N_ROWS];
__device__ float    g_xrow[N_ROWS];
__device__ unsigned g_min_an[N_ROWS];
__device__ unsigned g_max_ap[N_ROWS];
__device__ float    g_acc[2];
__device__ unsigned g_done = 0;

// ---------------- PTX helpers -------------------------------------------------
__device__ __forceinline__ uint32_t smem_u32(const void* p) {
    uint32_t a;
    asm("{ .reg .u64 t; cvta.to.shared.u64 t, %1; cvt.u32.u64 %0, t; }"
        : "=r"(a) : "l"(p));
    return a;
}
__device__ __forceinline__ void cpasync16(uint32_t dst, const void* src) {
    asm volatile("cp.async.cg.shared.global [%0], [%1], 16;" :: "r"(dst), "l"(src));
}
__device__ __forceinline__ void mma_f16_16x8x16(float* c, const uint32_t* a,
                                                const uint32_t* b) {
    asm volatile(
        "mma.sync.aligned.m16n8k16.row.col.f32.f16.f16.f32 "
        "{%0,%1,%2,%3}, {%4,%5,%6,%7}, {%8,%9}, {%0,%1,%2,%3};"
        : "+f"(c[0]), "+f"(c[1]), "+f"(c[2]), "+f"(c[3])
        : "r"(a[0]), "r"(a[1]), "r"(a[2]), "r"(a[3]), "r"(b[0]), "r"(b[1]));
}

// ---------------- block reductions (blockDim.x == 256) ------------------------
__device__ __forceinline__ float blockReduceSum(float v) {
    __shared__ float red[8];
    __shared__ float bc;
    int lane = threadIdx.x & 31, wid = threadIdx.x >> 5;
    #pragma unroll
    for (int s = 16; s; s >>= 1) v += __shfl_xor_sync(0xffffffffu, v, s);
    if (lane == 0) red[wid] = v;
    __syncthreads();
    if (threadIdx.x == 0) {
        float r = 0.f;
        #pragma unroll
        for (int w = 0; w < 8; ++w) r += red[w];
        bc = r;
    }
    __syncthreads();
    return bc;
}
__device__ __forceinline__ float blockReduceMax(float v) {
    __shared__ float red[8];
    __shared__ float bc;
    int lane = threadIdx.x & 31, wid = threadIdx.x >> 5;
    #pragma unroll
    for (int s = 16; s; s >>= 1) v = fmaxf(v, __shfl_xor_sync(0xffffffffu, v, s));
    if (lane == 0) red[wid] = v;
    __syncthreads();
    if (threadIdx.x == 0) {
        float r = -1e30f;
        #pragma unroll
        for (int w = 0; w < 8; ++w) r = fmaxf(r, red[w]);
        bc = r;
    }
    __syncthreads();
    return bc;
}

// ---------------- sq (of rounded feat) + fp16 convert + init -------------------
__global__ void sq_cvt_kernel(const float* __restrict__ feat) {
    int row = blockIdx.x;
    const float4* f = reinterpret_cast<const float4*>(feat + (size_t)row * D_FEAT);
    uint2* o = reinterpret_cast<uint2*>(g_feat_h + (size_t)row * D_FEAT);
    int t = threadIdx.x;
    float s = 0.f;
    #pragma unroll
    for (int q = 0; q < 2; ++q) {
        float4 v = f[t + q * 256];
        __half2 h0 = __floats2half2_rn(v.x, v.y);
        __half2 h1 = __floats2half2_rn(v.z, v.w);
        float2 r0 = __half22float2(h0);
        float2 r1 = __half22float2(h1);
        s += r0.x * r0.x + r0.y * r0.y + r1.x * r1.x + r1.y * r1.y;
        uint2 w;
        w.x = *reinterpret_cast<uint32_t*>(&h0);
        w.y = *reinterpret_cast<uint32_t*>(&h1);
        o[t + q * 256] = w;
    }
    s = blockReduceSum(s);
    if (t == 0) {
        g_sq[row] = s;
        g_min_an[row] = 0x7F800000u;
        g_max_ap[row] = 0u;
        if (row == 0) { g_acc[0] = 0.f; g_acc[1] = 0.f; }
    }
}

// ---------------- per-row cross-entropy ---------------------------------------
__global__ void xent_kernel(const float* __restrict__ logits,
                            const int*   __restrict__ targets) {
    int row = blockIdx.x;
    const float* lr = logits + (size_t)row * NUM_CLASSES;
    float m = -1e30f;
    for (int c = threadIdx.x; c < NUM_CLASSES; c += 256) m = fmaxf(m, lr[c]);
    m = blockReduceMax(m);
    float s = 0.f;
    for (int c = threadIdx.x; c < NUM_CLASSES; c += 256) s += expf(lr[c] - m);
    s = blockReduceSum(s);
    if (threadIdx.x == 0)
        g_xrow[row] = m + logf(s) - lr[targets[row]];
}

// ---------------- fp16 HMMA Gram GEMM + batch-hard mining ---------------------
__global__ __launch_bounds__(256, 2) void gemm_mine_hmma() {
    extern __shared__ __half sm[];
    const int tid  = threadIdx.x;
    const int lane = tid & 31;
    const int wid  = tid >> 5;
    const int wm   = wid >> 1;       // 0..3
    const int wn   = wid & 1;        // 0..1
    const int grp  = lane >> 2;      // 0..7
    const int tig  = lane & 3;       // 0..3

    int t = blockIdx.x, a = 0;
    while (t >= NTILE - a) { t -= NTILE - a; ++a; }
    const int b = a + t;
    const bool diag = (a == b);
    const int i0 = a * 128, j0 = b * 128;

    // loads: thread -> row (tid>>2) & rows +64; q = tid&3 selects 16B segment
    const int rw = tid >> 2;          // 0..63
    const int q  = tid & 3;           // 0..3
    const __half* pA = g_feat_h + (size_t)(i0 + rw) * D_FEAT + q * 8;
    const __half* pB = g_feat_h + (size_t)(j0 + rw) * D_FEAT + q * 8;
    const uint32_t base = smem_u32(sm);
    const uint32_t ldst = (uint32_t)(rw * LDH + q * 8) * 2;
    const uint32_t smA = base, smB = base + STAGES * STAGE_BYTES;

    auto load_chunk = [&](int s, int c) {
        const __half* aa = pA + c * KC;
        const __half* bb = pB + c * KC;
        const uint32_t da = smA + s * STAGE_BYTES + ldst;
        const uint32_t db = smB + s * STAGE_BYTES + ldst;
        cpasync16(da,                   aa);
        cpasync16(da + 64 * LDH * 2,    aa + (size_t)64 * D_FEAT);
        cpasync16(db,                   bb);
        cpasync16(db + 64 * LDH * 2,    bb + (size_t)64 * D_FEAT);
        asm volatile("cp.async.commit_group;" ::: "memory");
    };

    float acc[2][8][4];
    #pragma unroll
    for (int mf = 0; mf < 2; ++mf)
        #pragma unroll
        for (int nf = 0; nf < 8; ++nf)
            #pragma unroll
            for (int r = 0; r < 4; ++r) acc[mf][nf][r] = 0.f;

    load_chunk(0, 0);
    load_chunk(1, 1);

    for (int c = 0; c < CHUNKS; ++c) {
        const int s = c % STAGES;
        asm volatile("cp.async.wait_group 1;" ::: "memory");
        __syncthreads();
        if (c + STAGES - 1 < CHUNKS)
            load_chunk((c + STAGES - 1) % STAGES, c + STAGES - 1);

        const __half* As = sm + s * STAGE_HALFS;
        const __half* Bs = sm + STAGES * STAGE_HALFS + s * STAGE_HALFS;

        #pragma unroll
        for (int k16 = 0; k16 < 2; ++k16) {
            const int kb = k16 * 16;
            uint32_t av[2][4], bv[8][2];
            #pragma unroll
            for (int mf = 0; mf < 2; ++mf) {
                const __half* ap = As + (wm * 32 + mf * 16 + grp) * LDH + kb + 2 * tig;
                av[mf][0] = *reinterpret_cast<const uint32_t*>(ap);
                av[mf][1] = *reinterpret_cast<const uint32_t*>(ap + 8 * LDH);
                av[mf][2] = *reinterpret_cast<const uint32_t*>(ap + 8);
                av[mf][3] = *reinterpret_cast<const uint32_t*>(ap + 8 * LDH + 8);
            }
            #pragma unroll
            for (int nf = 0; nf < 8; ++nf) {
                const __half* bp = Bs + (wn * 64 + nf * 8 + grp) * LDH + kb + 2 * tig;
                bv[nf][0] = *reinterpret_cast<const uint32_t*>(bp);
                bv[nf][1] = *reinterpret_cast<const uint32_t*>(bp + 8);
            }
            #pragma unroll
            for (int mf = 0; mf < 2; ++mf)
                #pragma unroll
                for (int nf = 0; nf < 8; ++nf)
                    mma_f16_16x8x16(acc[mf][nf], av[mf], bv[nf]);
        }
    }

    // ---------------- epilogue: d^2 + batch-hard mining ----------------------
    __syncthreads();
    unsigned* rminS = (unsigned*)sm;
    unsigned* rmaxS = rminS + 128;
    unsigned* cminS = rminS + 256;
    if (tid < 128) {
        rminS[tid] = 0x7F800000u;
        rmaxS[tid] = 0u;
        cminS[tid] = 0x7F800000u;
    }
    __syncthreads();

    const int ib = i0 + wm * 32 + grp;
    const int jb = j0 + wn * 64 + 2 * tig;

    float sqj[8][2];
    #pragma unroll
    for (int nf = 0; nf < 8; ++nf) {
        sqj[nf][0] = __ldg(&g_sq[jb + nf * 8]);
        sqj[nf][1] = __ldg(&g_sq[jb + nf * 8 + 1]);
    }

    float cl[8][2];
    #pragma unroll
    for (int nf = 0; nf < 8; ++nf) { cl[nf][0] = 1e30f; cl[nf][1] = 1e30f; }

    #pragma unroll
    for (int mf = 0; mf < 2; ++mf) {
        const int iA = ib + mf * 16, iB = iA + 8;
        const float sq0 = __ldg(&g_sq[iA]);
        const float sq1 = __ldg(&g_sq[iB]);
        float rm0 = 1e30f, rm1 = 1e30f, rx0 = 0.f, rx1 = 0.f;
        #pragma unroll
        for (int nf = 0; nf < 8; ++nf) {
            #pragma unroll
            for (int p = 0; p < 2; ++p) {
                const int j = jb + nf * 8 + p;
                float d0 = fmaxf(sq0 + sqj[nf][p] - 2.f * acc[mf][nf][p],     0.f);
                float d1 = fmaxf(sq1 + sqj[nf][p] - 2.f * acc[mf][nf][2 + p], 0.f);
                if (diag) {
                    bool s0 = (iA >> 2) == (j >> 2);
                    bool s1 = (iB >> 2) == (j >> 2);
                    if (s0) rx0 = fmaxf(rx0, d0); else rm0 = fminf(rm0, d0);
                    if (s1) rx1 = fmaxf(rx1, d1); else rm1 = fminf(rm1, d1);
                } else {
                    rm0 = fminf(rm0, d0);
                    rm1 = fminf(rm1, d1);
                    cl[nf][p] = fminf(cl[nf][p], fminf(d0, d1));
                }
            }
        }
        #pragma unroll
        for (int sft = 1; sft <= 2; sft <<= 1) {
            rm0 = fminf(rm0, __shfl_xor_sync(0xffffffffu, rm0, sft));
            rm1 = fminf(rm1, __shfl_xor_sync(0xffffffffu, rm1, sft));
            rx0 = fmaxf(rx0, __shfl_xor_sync(0xffffffffu, rx0, sft));
            rx1 = fmaxf(rx1, __shfl_xor_sync(0xffffffffu, rx1, sft));
        }
        if (tig == 0) {
            atomicMin(&rminS[iA - i0], __float_as_uint(rm0));
            atomicMin(&rminS[iB - i0], __float_as_uint(rm1));
            if (diag) {
                atomicMax(&rmaxS[iA - i0], __float_as_uint(rx0));
                atomicMax(&rmaxS[iB - i0], __float_as_uint(rx1));
            }
        }
    }

    if (!diag) {
        #pragma unroll
        for (int nf = 0; nf < 8; ++nf)
            #pragma unroll
            for (int p = 0; p < 2; ++p) {
                float v = cl[nf][p];
                #pragma unroll
                for (int sft = 4; sft <= 16; sft <<= 1)
                    v = fminf(v, __shfl_xor_sync(0xffffffffu, v, sft));
                if (grp == 0)
                    atomicMin(&cminS[wn * 64 + nf * 8 + 2 * tig + p],
                              __float_as_uint(v));
            }
    }

    __syncthreads();
    if (tid < 128) {
        atomicMin(&g_min_an[i0 + tid], rminS[tid]);
        if (diag) atomicMax(&g_max_ap[i0 + tid], rmaxS[tid]);
        else      atomicMin(&g_min_an[j0 + tid], cminS[tid]);
    }
}

// ---------------- final scalar (parallel, last-block-writes) -------------------
__global__ void finalize_kernel(float* __restrict__ out) {
    const int i = blockIdx.x * 256 + threadIdx.x;
    float xs = g_xrow[i];
    float ap = sqrtf(fmaxf(__uint_as_float(g_max_ap[i]), 1e-12f));
    float an = sqrtf(fmaxf(__uint_as_float(g_min_an[i]), 1e-12f));
    float ts = fmaxf(ap - an + MARGIN1, 0.f);
    xs = blockReduceSum(xs);
    ts = blockReduceSum(ts);
    if (threadIdx.x == 0) {
        atomicAdd(&g_acc[0], xs);
        atomicAdd(&g_acc[1], ts);
        __threadfence();
        unsigned old = atomicInc(&g_done, FIN_BLOCKS - 1);
        if (old == FIN_BLOCKS - 1)
            out[0] = (g_acc[0] + g_acc[1]) / (float)N_ROWS;
    }
}

// ---------------- launch --------------------------------------------------------
extern "C" void kernel_launch(void* const* d_in, const int* in_sizes, int n_in,
                              void* d_out, int out_size) {
    const float* logits  = (const float*)d_in[0];
    const float* feat    = (const float*)d_in[1];
    const int*   targets = (const int*)d_in[2];
    float* out = (float*)d_out;

    cudaFuncSetAttribute(gemm_mine_hmma,
                         cudaFuncAttributeMaxDynamicSharedMemorySize, SMEM_BYTES);

    sq_cvt_kernel<<<N_ROWS, 256>>>(feat);
    xent_kernel<<<N_ROWS, 256>>>(logits, targets);
    gemm_mine_hmma<<<NBLOCKS_TRI, 256, SMEM_BYTES>>>();
    finalize_kernel<<<FIN_BLOCKS, 256>>>(out);
}